// round 15
// baseline (speedup 1.0000x reference)
#include <cuda_runtime.h>
#include <cuda_fp16.h>

#define N_NODES 100000
#define E_INTRA 1000000
#define E_INTER 500000
#define E_TOT   (E_INTRA + E_INTER)
#define NSEG    400000
#define NB_SCAN 391
#define SHIFT   10.0f

// ---------------- side stream (created once, pre-main) ----------------
struct SideStream {
    cudaStream_t s2 = nullptr;
    cudaEvent_t  e1 = nullptr, e2 = nullptr;
    bool ok = false;
    SideStream() {
        ok = (cudaStreamCreateWithFlags(&s2, cudaStreamNonBlocking) == cudaSuccess)
          && (cudaEventCreateWithFlags(&e1, cudaEventDisableTiming) == cudaSuccess)
          && (cudaEventCreateWithFlags(&e2, cudaEventDisableTiming) == cudaSuccess);
    }
};
static SideStream g_ss;

// ---------------- scratch ----------------
__device__ __half  g_wcat[64 * 1024];   // [o][p*256+h*64+c] fp16 (pre-transposed, /4)
__device__ float   g_as[N_NODES * 16];
__device__ float   g_ad[N_NODES * 16];
__device__ float   g_fold[64 * 32];
__device__ float   g_bias[64];
__device__ int     g_cnt[NSEG];
__device__ int     g_off[NSEG];
__device__ int     g_cur[NSEG];
__device__ int     g_bsum[NB_SCAN];
__device__ int     g_esrc[E_TOT];

// ---------------- fp16 mma helper ----------------
__device__ __forceinline__ void mma_f16(float* c, const unsigned* a,
                                        unsigned b0, unsigned b1) {
    asm("mma.sync.aligned.m16n8k16.row.col.f32.f16.f16.f32 "
        "{%0,%1,%2,%3},{%4,%5,%6,%7},{%8,%9},{%0,%1,%2,%3};"
        : "+f"(c[0]), "+f"(c[1]), "+f"(c[2]), "+f"(c[3])
        : "r"(a[0]), "r"(a[1]), "r"(a[2]), "r"(a[3]), "r"(b0), "r"(b1));
}

// ---------------- small setup kernels ----------------
__global__ void zero_k() {
    int i = blockIdx.x * blockDim.x + threadIdx.x;
    if (i < NSEG) g_cnt[i] = 0;
}

// Wcat[o][k], k=(p,h,c): W_p[c, h*64+o] * 0.25 (head-avg folded in)
__global__ void wcat_k(const float* __restrict__ Wi, const float* __restrict__ Ww) {
    int idx = blockIdx.x * blockDim.x + threadIdx.x;
    if (idx >= 64 * 1024) return;
    int o = idx >> 10, k = idx & 1023;
    int p = k >> 8, h = (k >> 6) & 3, c = k & 63;
    float v = (p < 3) ? Wi[p * 16384 + c * 256 + h * 64 + o]
                      : Ww[c * 256 + h * 64 + o];
    g_wcat[idx] = __float2half_rn(0.25f * v);
}

__global__ void fold_k(const float* __restrict__ Wi, const float* __restrict__ asi,
                       const float* __restrict__ adi, const float* __restrict__ Ww,
                       const float* __restrict__ asw, const float* __restrict__ adw,
                       const float* __restrict__ bi, const float* __restrict__ bw) {
    int idx = blockIdx.x * blockDim.x + threadIdx.x;
    if (idx < 64) g_bias[idx] = bi[idx] + bi[64 + idx] + bi[128 + idx] + bw[idx];
    if (idx >= 64 * 32) return;
    int f = idx >> 5, o = idx & 31;
    int sd = o >> 4, p = (o >> 2) & 3, h = o & 3;
    const float* W = (p < 3) ? (Wi + p * 64 * 256) : Ww;
    const float* att;
    if (p < 3) att = (sd ? adi : asi) + p * 4 * 64 + h * 64;
    else       att = (sd ? adw : asw) + h * 64;
    const float* wr = W + f * 256 + h * 64;
    float s = 0.f;
    #pragma unroll 16
    for (int c = 0; c < 64; c++) s += wr[c] * att[c];
    g_fold[f * 32 + o] = s;
}

__global__ __launch_bounds__(256) void asd_k(const float* __restrict__ x) {
    __shared__ float sf[64 * 32];
    for (int i = threadIdx.x; i < 2048; i += 256) sf[i] = g_fold[i];
    __syncthreads();
    int n = blockIdx.x * blockDim.x + threadIdx.x;
    if (n >= N_NODES) return;
    float acc[32];
    #pragma unroll
    for (int o = 0; o < 32; o++) acc[o] = 0.f;
    const float4* xr = (const float4*)(x + (size_t)n * 64);
    #pragma unroll
    for (int f4 = 0; f4 < 16; f4++) {
        float4 xv = __ldg(xr + f4);
        int f = f4 * 4;
        #pragma unroll
        for (int o = 0; o < 32; o++) {
            acc[o] += xv.x * sf[(f + 0) * 32 + o] + xv.y * sf[(f + 1) * 32 + o]
                    + xv.z * sf[(f + 2) * 32 + o] + xv.w * sf[(f + 3) * 32 + o];
        }
    }
    float4* as4 = (float4*)(g_as + n * 16);
    float4* ad4 = (float4*)(g_ad + n * 16);
    #pragma unroll
    for (int q = 0; q < 4; q++) {
        as4[q] = make_float4(acc[q * 4 + 0], acc[q * 4 + 1], acc[q * 4 + 2], acc[q * 4 + 3]);
        ad4[q] = make_float4(acc[16 + q * 4 + 0], acc[16 + q * 4 + 1], acc[16 + q * 4 + 2], acc[16 + q * 4 + 3]);
    }
}

// ---------------- CSR build ----------------
__global__ void hist_k(const int* __restrict__ mod, const int* __restrict__ idst,
                       const int* __restrict__ wdst) {
    int e = blockIdx.x * blockDim.x + threadIdx.x;
    if (e >= E_TOT) return;
    int key;
    if (e < E_INTRA) key = __ldg(mod + e) * N_NODES + __ldg(idst + e);
    else             key = 3 * N_NODES + __ldg(wdst + e - E_INTRA);
    atomicAdd(&g_cnt[key], 1);
}

__global__ __launch_bounds__(256) void scan1_k() {
    __shared__ int sw[8];
    int b = blockIdx.x, t = threadIdx.x;
    int lane = t & 31, wid = t >> 5;
    int base = b * 1024 + t * 4;
    int v0 = (base + 0 < NSEG) ? g_cnt[base + 0] : 0;
    int v1 = (base + 1 < NSEG) ? g_cnt[base + 1] : 0;
    int v2 = (base + 2 < NSEG) ? g_cnt[base + 2] : 0;
    int v3 = (base + 3 < NSEG) ? g_cnt[base + 3] : 0;
    int tsum = v0 + v1 + v2 + v3;
    int incl = tsum;
    #pragma unroll
    for (int o = 1; o < 32; o <<= 1) {
        int n = __shfl_up_sync(0xffffffffu, incl, o);
        if (lane >= o) incl += n;
    }
    if (lane == 31) sw[wid] = incl;
    __syncthreads();
    int wbase = 0;
    for (int i = 0; i < 8; i++) if (i < wid) wbase += sw[i];
    int texcl = wbase + incl - tsum;
    if (base + 0 < NSEG) g_off[base + 0] = texcl;
    if (base + 1 < NSEG) g_off[base + 1] = texcl + v0;
    if (base + 2 < NSEG) g_off[base + 2] = texcl + v0 + v1;
    if (base + 3 < NSEG) g_off[base + 3] = texcl + v0 + v1 + v2;
    if (t == 255) g_bsum[b] = texcl + tsum;
}

__global__ __launch_bounds__(512) void scan2_k() {
    __shared__ int sw[16];
    int t = threadIdx.x, lane = t & 31, wid = t >> 5;
    int v = (t < NB_SCAN) ? g_bsum[t] : 0;
    int incl = v;
    #pragma unroll
    for (int o = 1; o < 32; o <<= 1) {
        int n = __shfl_up_sync(0xffffffffu, incl, o);
        if (lane >= o) incl += n;
    }
    if (lane == 31) sw[wid] = incl;
    __syncthreads();
    int wbase = 0;
    for (int i = 0; i < 16; i++) if (i < wid) wbase += sw[i];
    if (t < NB_SCAN) g_bsum[t] = wbase + incl - v;
}

__global__ void scan3_k() {
    int i = blockIdx.x * blockDim.x + threadIdx.x;
    if (i >= NSEG) return;
    int o = g_off[i] + g_bsum[i >> 10];
    g_off[i] = o;
    g_cur[i] = o;
}

__global__ void scat_k(const int* __restrict__ mod,
                       const int* __restrict__ isrc, const int* __restrict__ idst,
                       const int* __restrict__ wsrc, const int* __restrict__ wdst) {
    int e = blockIdx.x * blockDim.x + threadIdx.x;
    if (e >= E_TOT) return;
    int key, s;
    if (e < E_INTRA) {
        key = __ldg(mod + e) * N_NODES + __ldg(idst + e);
        s = __ldg(isrc + e);
    } else {
        key = 3 * N_NODES + __ldg(wdst + e - E_INTRA);
        s = __ldg(wsrc + e - E_INTRA);
    }
    int pos = atomicAdd(&g_cur[key], 1);
    g_esrc[pos] = s;
}

// ---------------- FUSED aggregate + GEMM ----------------
// Block owns 128 dst rows. Per pass p: 8 warps aggregate the Y-tile
// [128 rows][256 cols] fp16 into smem (warp per segment, R11-proven two-phase
// inner shape), then 8 warps mma-accumulate ytile @ WcatChunk^T into out-regs.
// After 4 passes: +bias, store. Y never touches DRAM (saves 410 MB round-trip).
#define FP2  132   // ytile pitch in half2 (128 data + 4 pad)
#define CPF  68    // csm pitch in floats (epilogue overlay on ytile)
#define YT_BYTES  (128 * FP2 * 4)
#define WS2_BYTES (64 * FP2 * 4)
#define FUSED_SMEM (YT_BYTES + WS2_BYTES + 256)

__device__ __forceinline__ float4 edge_p(int s, float4 ad, int aoff) {
    float4 as = *(const float4*)(g_as + s * 16 + aoff);
    float v0 = as.x + ad.x; v0 = v0 > 0.f ? v0 : 0.2f * v0;
    float v1 = as.y + ad.y; v1 = v1 > 0.f ? v1 : 0.2f * v1;
    float v2 = as.z + ad.z; v2 = v2 > 0.f ? v2 : 0.2f * v2;
    float v3 = as.w + ad.w; v3 = v3 > 0.f ? v3 : 0.2f * v3;
    return make_float4(__expf(v0 - SHIFT), __expf(v1 - SHIFT),
                       __expf(v2 - SHIFT), __expf(v3 - SHIFT));
}

__global__ __launch_bounds__(256) void fused_k(const float* __restrict__ x,
                                               float* __restrict__ out) {
    extern __shared__ char smem_c[];
    __half2* yt  = (__half2*)smem_c;                  // [128][FP2]
    __half2* ws  = (__half2*)(smem_c + YT_BYTES);     // [64][FP2]
    float*   sb  = (float*)(smem_c + YT_BYTES + WS2_BYTES);
    float*   csm = (float*)smem_c;                    // epilogue overlay on yt

    __shared__ float4 pbuf[8][32];
    __shared__ int    sbuf[8][32];

    int tid = threadIdx.x;
    int lane = tid & 31, w = tid >> 5;
    int gid = lane >> 2, tig = lane & 3;
    int warp_m = w >> 1, warp_n = w & 1;     // mma: 4 x 2 warp grid
    int rbase = blockIdx.x * 128;
    if (tid < 64) sb[tid] = g_bias[tid];

    float acc[2][4][4];
    #pragma unroll
    for (int mf = 0; mf < 2; mf++)
        #pragma unroll
        for (int nf = 0; nf < 4; nf++)
            #pragma unroll
            for (int q = 0; q < 4; q++) acc[mf][nf][q] = 0.f;

    for (int pass = 0; pass < 4; pass++) {
        int aoff = pass * 4;

        // load Wcat chunk [64][256 halfs] -> ws (independent smem region)
        #pragma unroll
        for (int i = 0; i < 8; i++) {
            int slot = tid + i * 256;               // 2048 uint4 slots
            int o = slot >> 5, q = slot & 31;
            *(uint4*)&ws[o * FP2 + q * 4] =
                *(const uint4*)(g_wcat + o * 1024 + pass * 256 + q * 8);
        }

        // aggregate 16 segments per warp into ytile
        for (int i = 0; i < 16; i++) {
            int r = w * 16 + i;
            int d = rbase + r;
            __half2* yrow = yt + r * FP2;
            int deg = 0, off0 = 0;
            if (d < N_NODES) {
                int seg = pass * N_NODES + d;
                off0 = g_off[seg];
                int off1 = (seg + 1 < NSEG) ? g_off[seg + 1] : E_TOT;
                deg = off1 - off0;
            }
            if (deg == 0) {
                __half2 z = __floats2half2_rn(0.f, 0.f);
                #pragma unroll
                for (int h = 0; h < 4; h++) yrow[h * 32 + lane] = z;
                continue;
            }
            float4 ad = *(const float4*)(g_ad + d * 16 + aoff);

            // phase A: lane-parallel logits; stash first 32
            float d0 = 0.f, d1 = 0.f, d2 = 0.f, d3 = 0.f;
            for (int j = lane; j < deg; j += 32) {
                int s = g_esrc[off0 + j];
                float4 p = edge_p(s, ad, aoff);
                if (j < 32) { pbuf[w][j] = p; sbuf[w][j] = s; }
                d0 += p.x; d1 += p.y; d2 += p.z; d3 += p.w;
            }
            #pragma unroll
            for (int o = 16; o > 0; o >>= 1) {
                d0 += __shfl_xor_sync(0xffffffffu, d0, o);
                d1 += __shfl_xor_sync(0xffffffffu, d1, o);
                d2 += __shfl_xor_sync(0xffffffffu, d2, o);
                d3 += __shfl_xor_sync(0xffffffffu, d3, o);
            }
            __syncwarp();
            float i0 = 1.f / fmaxf(d0, 1e-16f);   // 0.25 folded into Wcat
            float i1 = 1.f / fmaxf(d1, 1e-16f);
            float i2 = 1.f / fmaxf(d2, 1e-16f);
            float i3 = 1.f / fmaxf(d3, 1e-16f);

            // phase B: lane covers x cols 2*lane, 2*lane+1 (x L2-resident)
            float c00 = 0.f, c01 = 0.f, c10 = 0.f, c11 = 0.f;
            float c20 = 0.f, c21 = 0.f, c30 = 0.f, c31 = 0.f;
            for (int j = 0; j < deg; j++) {
                int s; float4 p;
                if (j < 32) { s = sbuf[w][j]; p = pbuf[w][j]; }
                else        { s = g_esrc[off0 + j]; p = edge_p(s, ad, aoff); }
                float2 xv = *(const float2*)(x + (size_t)s * 64 + 2 * lane);
                c00 += p.x * xv.x; c01 += p.x * xv.y;
                c10 += p.y * xv.x; c11 += p.y * xv.y;
                c20 += p.z * xv.x; c21 += p.z * xv.y;
                c30 += p.w * xv.x; c31 += p.w * xv.y;
            }
            yrow[0 * 32 + lane] = __floats2half2_rn(c00 * i0, c01 * i0);
            yrow[1 * 32 + lane] = __floats2half2_rn(c10 * i1, c11 * i1);
            yrow[2 * 32 + lane] = __floats2half2_rn(c20 * i2, c21 * i2);
            yrow[3 * 32 + lane] = __floats2half2_rn(c30 * i3, c31 * i3);
        }
        __syncthreads();   // ytile + ws ready

        // mma: acc += ytile[128][256] @ ws[64][256]^T (K=256 = 16 x k16)
        #pragma unroll
        for (int ks = 0; ks < 16; ks++) {
            int kc = ks * 8;                       // half2 units
            unsigned a[2][4];
            #pragma unroll
            for (int mf = 0; mf < 2; mf++) {
                int arow = warp_m * 32 + mf * 16 + gid;
                a[mf][0] = *(unsigned*)&yt[arow * FP2 + kc + tig];
                a[mf][1] = *(unsigned*)&yt[(arow + 8) * FP2 + kc + tig];
                a[mf][2] = *(unsigned*)&yt[arow * FP2 + kc + tig + 4];
                a[mf][3] = *(unsigned*)&yt[(arow + 8) * FP2 + kc + tig + 4];
            }
            #pragma unroll
            for (int nf = 0; nf < 4; nf++) {
                int ncol = warp_n * 32 + nf * 8 + gid;
                unsigned b0 = *(unsigned*)&ws[ncol * FP2 + kc + tig];
                unsigned b1 = *(unsigned*)&ws[ncol * FP2 + kc + tig + 4];
                #pragma unroll
                for (int mf = 0; mf < 2; mf++)
                    mma_f16(acc[mf][nf], a[mf], b0, b1);
            }
        }
        __syncthreads();   // mma reads done before next pass overwrites
    }

    // epilogue: stage fp32 C in csm (overlay), then coalesced biased store
    #pragma unroll
    for (int mf = 0; mf < 2; mf++) {
        int r = warp_m * 32 + mf * 16 + gid;
        #pragma unroll
        for (int nf = 0; nf < 4; nf++) {
            int c = warp_n * 32 + nf * 8 + 2 * tig;
            *(float2*)&csm[r * CPF + c]       = make_float2(acc[mf][nf][0], acc[mf][nf][1]);
            *(float2*)&csm[(r + 8) * CPF + c] = make_float2(acc[mf][nf][2], acc[mf][nf][3]);
        }
    }
    __syncthreads();

    #pragma unroll
    for (int i = 0; i < 8; i++) {
        int slot = tid + i * 256;
        int row = slot >> 4, q = slot & 15;
        int grow = rbase + row;
        if (grow < N_NODES) {
            float4 v;
            v.x = csm[row * CPF + q * 4 + 0] + sb[q * 4 + 0];
            v.y = csm[row * CPF + q * 4 + 1] + sb[q * 4 + 1];
            v.z = csm[row * CPF + q * 4 + 2] + sb[q * 4 + 2];
            v.w = csm[row * CPF + q * 4 + 3] + sb[q * 4 + 3];
            *(float4*)(out + (size_t)grow * 64 + q * 4) = v;
        }
    }
}

// ---------------- launch ----------------
extern "C" void kernel_launch(void* const* d_in, const int* in_sizes, int n_in,
                              void* d_out, int out_size) {
    const float* x        = (const float*)d_in[0];
    const int*   modality = (const int*)d_in[1];
    const int*   isrc     = (const int*)d_in[2];
    const int*   idst     = (const int*)d_in[3];
    const int*   wsrc     = (const int*)d_in[4];
    const int*   wdst     = (const int*)d_in[5];
    const float* W_intra  = (const float*)d_in[6];
    const float* as_i     = (const float*)d_in[7];
    const float* ad_i     = (const float*)d_in[8];
    const float* b_i      = (const float*)d_in[9];
    const float* W_inter  = (const float*)d_in[10];
    const float* as_w     = (const float*)d_in[11];
    const float* ad_w     = (const float*)d_in[12];
    const float* b_w      = (const float*)d_in[13];
    float* out = (float*)d_out;

    cudaFuncSetAttribute(fused_k, cudaFuncAttributeMaxDynamicSharedMemorySize, FUSED_SMEM);

    if (g_ss.ok) {
        cudaEventRecord(g_ss.e1, 0);
        cudaStreamWaitEvent(g_ss.s2, g_ss.e1, 0);

        // s2: CSR build + Wcat (independent of x-chain)
        zero_k<<<(NSEG + 255) / 256, 256, 0, g_ss.s2>>>();
        wcat_k<<<(64 * 1024 + 255) / 256, 256, 0, g_ss.s2>>>(W_intra, W_inter);
        hist_k<<<(E_TOT + 255) / 256, 256, 0, g_ss.s2>>>(modality, idst, wdst);
        scan1_k<<<NB_SCAN, 256, 0, g_ss.s2>>>();
        scan2_k<<<1, 512, 0, g_ss.s2>>>();
        scan3_k<<<(NSEG + 255) / 256, 256, 0, g_ss.s2>>>();
        scat_k<<<(E_TOT + 255) / 256, 256, 0, g_ss.s2>>>(modality, isrc, idst, wsrc, wdst);
        cudaEventRecord(g_ss.e2, g_ss.s2);

        // main: logits chain, join CSR, then single fused kernel
        fold_k<<<8, 256>>>(W_intra, as_i, ad_i, W_inter, as_w, ad_w, b_i, b_w);
        asd_k<<<(N_NODES + 255) / 256, 256>>>(x);
        cudaStreamWaitEvent(0, g_ss.e2, 0);
        fused_k<<<(N_NODES + 127) / 128, 256, FUSED_SMEM>>>(x, out);
    } else {
        zero_k<<<(NSEG + 255) / 256, 256>>>();
        wcat_k<<<(64 * 1024 + 255) / 256, 256>>>(W_intra, W_inter);
        fold_k<<<8, 256>>>(W_intra, as_i, ad_i, W_inter, as_w, ad_w, b_i, b_w);
        asd_k<<<(N_NODES + 255) / 256, 256>>>(x);
        hist_k<<<(E_TOT + 255) / 256, 256>>>(modality, idst, wdst);
        scan1_k<<<NB_SCAN, 256>>>();
        scan2_k<<<1, 512>>>();
        scan3_k<<<(NSEG + 255) / 256, 256>>>();
        scat_k<<<(E_TOT + 255) / 256, 256>>>(modality, isrc, idst, wsrc, wdst);
        fused_k<<<(N_NODES + 127) / 128, 256, FUSED_SMEM>>>(x, out);
    }
}

// round 16
// speedup vs baseline: 1.2345x; 1.2345x over previous
#include <cuda_runtime.h>
#include <cuda_fp16.h>

#define N_NODES 100000
#define E_INTRA 1000000
#define E_INTER 500000
#define E_TOT   (E_INTRA + E_INTER)
#define NSEG    400000
#define NB_SCAN 391
#define SHIFT   10.0f
#define NCHUNK  4
#define CHUNK   (N_NODES / NCHUNK)     // 25000

// ---------------- side stream (created once, pre-main) ----------------
struct SideStream {
    cudaStream_t s2 = nullptr;
    cudaEvent_t  e1 = nullptr, e2 = nullptr;
    bool ok = false;
    SideStream() {
        ok = (cudaStreamCreateWithFlags(&s2, cudaStreamNonBlocking) == cudaSuccess)
          && (cudaEventCreateWithFlags(&e1, cudaEventDisableTiming) == cudaSuccess)
          && (cudaEventCreateWithFlags(&e2, cudaEventDisableTiming) == cudaSuccess);
    }
};
static SideStream g_ss;

// ---------------- scratch ----------------
__device__ __half  g_y[(size_t)N_NODES * 1024];   // [n][p*256+h*64+c] fp16, 205MB
__device__ __half  g_wcat[64 * 1024];             // [o][p*256+h*64+c] fp16 (pre-transposed, /4)
__device__ float   g_as[N_NODES * 16];
__device__ float   g_ad[N_NODES * 16];
__device__ float   g_fold[64 * 32];
__device__ float   g_bias[64];
__device__ int     g_cnt[NSEG];
__device__ int     g_off[NSEG];
__device__ int     g_cur[NSEG];
__device__ int     g_bsum[NB_SCAN];
__device__ int     g_esrc[E_TOT];

// ---------------- fp16 mma helper ----------------
__device__ __forceinline__ void mma_f16(float* c, const unsigned* a,
                                        unsigned b0, unsigned b1) {
    asm("mma.sync.aligned.m16n8k16.row.col.f32.f16.f16.f32 "
        "{%0,%1,%2,%3},{%4,%5,%6,%7},{%8,%9},{%0,%1,%2,%3};"
        : "+f"(c[0]), "+f"(c[1]), "+f"(c[2]), "+f"(c[3])
        : "r"(a[0]), "r"(a[1]), "r"(a[2]), "r"(a[3]), "r"(b0), "r"(b1));
}

// ---------------- small setup kernels ----------------
__global__ void zero_k() {
    int i = blockIdx.x * blockDim.x + threadIdx.x;
    if (i < NSEG) g_cnt[i] = 0;
}

// Wcat[o][k], k=(p,h,c): W_p[c, h*64+o] * 0.25 (head-avg folded in)
__global__ void wcat_k(const float* __restrict__ Wi, const float* __restrict__ Ww) {
    int idx = blockIdx.x * blockDim.x + threadIdx.x;
    if (idx >= 64 * 1024) return;
    int o = idx >> 10, k = idx & 1023;
    int p = k >> 8, h = (k >> 6) & 3, c = k & 63;
    float v = (p < 3) ? Wi[p * 16384 + c * 256 + h * 64 + o]
                      : Ww[c * 256 + h * 64 + o];
    g_wcat[idx] = __float2half_rn(0.25f * v);
}

__global__ void fold_k(const float* __restrict__ Wi, const float* __restrict__ asi,
                       const float* __restrict__ adi, const float* __restrict__ Ww,
                       const float* __restrict__ asw, const float* __restrict__ adw,
                       const float* __restrict__ bi, const float* __restrict__ bw) {
    int idx = blockIdx.x * blockDim.x + threadIdx.x;
    if (idx < 64) g_bias[idx] = bi[idx] + bi[64 + idx] + bi[128 + idx] + bw[idx];
    if (idx >= 64 * 32) return;
    int f = idx >> 5, o = idx & 31;
    int sd = o >> 4, p = (o >> 2) & 3, h = o & 3;
    const float* W = (p < 3) ? (Wi + p * 64 * 256) : Ww;
    const float* att;
    if (p < 3) att = (sd ? adi : asi) + p * 4 * 64 + h * 64;
    else       att = (sd ? adw : asw) + h * 64;
    const float* wr = W + f * 256 + h * 64;
    float s = 0.f;
    #pragma unroll 16
    for (int c = 0; c < 64; c++) s += wr[c] * att[c];
    g_fold[f * 32 + o] = s;
}

__global__ __launch_bounds__(256) void asd_k(const float* __restrict__ x) {
    __shared__ float sf[64 * 32];
    for (int i = threadIdx.x; i < 2048; i += 256) sf[i] = g_fold[i];
    __syncthreads();
    int n = blockIdx.x * blockDim.x + threadIdx.x;
    if (n >= N_NODES) return;
    float acc[32];
    #pragma unroll
    for (int o = 0; o < 32; o++) acc[o] = 0.f;
    const float4* xr = (const float4*)(x + (size_t)n * 64);
    #pragma unroll
    for (int f4 = 0; f4 < 16; f4++) {
        float4 xv = __ldg(xr + f4);
        int f = f4 * 4;
        #pragma unroll
        for (int o = 0; o < 32; o++) {
            acc[o] += xv.x * sf[(f + 0) * 32 + o] + xv.y * sf[(f + 1) * 32 + o]
                    + xv.z * sf[(f + 2) * 32 + o] + xv.w * sf[(f + 3) * 32 + o];
        }
    }
    float4* as4 = (float4*)(g_as + n * 16);
    float4* ad4 = (float4*)(g_ad + n * 16);
    #pragma unroll
    for (int q = 0; q < 4; q++) {
        as4[q] = make_float4(acc[q * 4 + 0], acc[q * 4 + 1], acc[q * 4 + 2], acc[q * 4 + 3]);
        ad4[q] = make_float4(acc[16 + q * 4 + 0], acc[16 + q * 4 + 1], acc[16 + q * 4 + 2], acc[16 + q * 4 + 3]);
    }
}

// ---------------- CSR build ----------------
__global__ void hist_k(const int* __restrict__ mod, const int* __restrict__ idst,
                       const int* __restrict__ wdst) {
    int e = blockIdx.x * blockDim.x + threadIdx.x;
    if (e >= E_TOT) return;
    int key;
    if (e < E_INTRA) key = __ldg(mod + e) * N_NODES + __ldg(idst + e);
    else             key = 3 * N_NODES + __ldg(wdst + e - E_INTRA);
    atomicAdd(&g_cnt[key], 1);
}

__global__ __launch_bounds__(256) void scan1_k() {
    __shared__ int sw[8];
    int b = blockIdx.x, t = threadIdx.x;
    int lane = t & 31, wid = t >> 5;
    int base = b * 1024 + t * 4;
    int v0 = (base + 0 < NSEG) ? g_cnt[base + 0] : 0;
    int v1 = (base + 1 < NSEG) ? g_cnt[base + 1] : 0;
    int v2 = (base + 2 < NSEG) ? g_cnt[base + 2] : 0;
    int v3 = (base + 3 < NSEG) ? g_cnt[base + 3] : 0;
    int tsum = v0 + v1 + v2 + v3;
    int incl = tsum;
    #pragma unroll
    for (int o = 1; o < 32; o <<= 1) {
        int n = __shfl_up_sync(0xffffffffu, incl, o);
        if (lane >= o) incl += n;
    }
    if (lane == 31) sw[wid] = incl;
    __syncthreads();
    int wbase = 0;
    for (int i = 0; i < 8; i++) if (i < wid) wbase += sw[i];
    int texcl = wbase + incl - tsum;
    if (base + 0 < NSEG) g_off[base + 0] = texcl;
    if (base + 1 < NSEG) g_off[base + 1] = texcl + v0;
    if (base + 2 < NSEG) g_off[base + 2] = texcl + v0 + v1;
    if (base + 3 < NSEG) g_off[base + 3] = texcl + v0 + v1 + v2;
    if (t == 255) g_bsum[b] = texcl + tsum;
}

__global__ __launch_bounds__(512) void scan2_k() {
    __shared__ int sw[16];
    int t = threadIdx.x, lane = t & 31, wid = t >> 5;
    int v = (t < NB_SCAN) ? g_bsum[t] : 0;
    int incl = v;
    #pragma unroll
    for (int o = 1; o < 32; o <<= 1) {
        int n = __shfl_up_sync(0xffffffffu, incl, o);
        if (lane >= o) incl += n;
    }
    if (lane == 31) sw[wid] = incl;
    __syncthreads();
    int wbase = 0;
    for (int i = 0; i < 16; i++) if (i < wid) wbase += sw[i];
    if (t < NB_SCAN) g_bsum[t] = wbase + incl - v;
}

__global__ void scan3_k() {
    int i = blockIdx.x * blockDim.x + threadIdx.x;
    if (i >= NSEG) return;
    int o = g_off[i] + g_bsum[i >> 10];
    g_off[i] = o;
    g_cur[i] = o;
}

__global__ void scat_k(const int* __restrict__ mod,
                       const int* __restrict__ isrc, const int* __restrict__ idst,
                       const int* __restrict__ wsrc, const int* __restrict__ wdst) {
    int e = blockIdx.x * blockDim.x + threadIdx.x;
    if (e >= E_TOT) return;
    int key, s;
    if (e < E_INTRA) {
        key = __ldg(mod + e) * N_NODES + __ldg(idst + e);
        s = __ldg(isrc + e);
    } else {
        key = 3 * N_NODES + __ldg(wdst + e - E_INTRA);
        s = __ldg(wsrc + e - E_INTRA);
    }
    int pos = atomicAdd(&g_cur[key], 1);
    g_esrc[pos] = s;
}

// ---------------- x-space softmax aggregation for a row chunk ----------------
__device__ __forceinline__ float4 edge_p(int s, float4 ad, int aoff) {
    float4 as = *(const float4*)(g_as + s * 16 + aoff);
    float v0 = as.x + ad.x; v0 = v0 > 0.f ? v0 : 0.2f * v0;
    float v1 = as.y + ad.y; v1 = v1 > 0.f ? v1 : 0.2f * v1;
    float v2 = as.z + ad.z; v2 = v2 > 0.f ? v2 : 0.2f * v2;
    float v3 = as.w + ad.w; v3 = v3 > 0.f ? v3 : 0.2f * v3;
    return make_float4(__expf(v0 - SHIFT), __expf(v1 - SHIFT),
                       __expf(v2 - SHIFT), __expf(v3 - SHIFT));
}

__global__ __launch_bounds__(128) void aggx_k(const float* __restrict__ x, int row0) {
    __shared__ float4 pbuf[4][32];
    __shared__ int    sbuf[4][32];
    int pass = blockIdx.y;
    int w = threadIdx.x >> 5;
    int d = row0 + blockIdx.x * 4 + w;   // CHUNK divisible by 4: exact
    int lane = threadIdx.x & 31;
    int seg = pass * N_NODES + d;
    int off0 = g_off[seg];
    int off1 = (seg + 1 < NSEG) ? g_off[seg + 1] : E_TOT;
    int deg = off1 - off0;
    int aoff = pass * 4;
    __half2* yrow = (__half2*)(g_y + (size_t)d * 1024 + pass * 256);

    if (deg == 0) {
        __half2 z = __floats2half2_rn(0.f, 0.f);
        #pragma unroll
        for (int h = 0; h < 4; h++) yrow[h * 32 + lane] = z;
        return;
    }

    float4 ad = *(const float4*)(g_ad + d * 16 + aoff);

    // phase A: lane-parallel edge logits; stash (p, s) for first 32 edges
    float d0 = 0.f, d1 = 0.f, d2 = 0.f, d3 = 0.f;
    for (int j = lane; j < deg; j += 32) {
        int s = g_esrc[off0 + j];
        float4 p = edge_p(s, ad, aoff);
        if (j < 32) { pbuf[w][j] = p; sbuf[w][j] = s; }
        d0 += p.x; d1 += p.y; d2 += p.z; d3 += p.w;
    }
    #pragma unroll
    for (int o = 16; o > 0; o >>= 1) {
        d0 += __shfl_xor_sync(0xffffffffu, d0, o);
        d1 += __shfl_xor_sync(0xffffffffu, d1, o);
        d2 += __shfl_xor_sync(0xffffffffu, d2, o);
        d3 += __shfl_xor_sync(0xffffffffu, d3, o);
    }
    __syncwarp();
    float i0 = 1.f / fmaxf(d0, 1e-16f);   // 0.25 folded into Wcat
    float i1 = 1.f / fmaxf(d1, 1e-16f);
    float i2 = 1.f / fmaxf(d2, 1e-16f);
    float i3 = 1.f / fmaxf(d3, 1e-16f);

    // phase B: lane covers x cols 2*lane, 2*lane+1 (x L2-resident, 25.6MB)
    float c00 = 0.f, c01 = 0.f, c10 = 0.f, c11 = 0.f;
    float c20 = 0.f, c21 = 0.f, c30 = 0.f, c31 = 0.f;
    for (int j = 0; j < deg; j++) {
        int s; float4 p;
        if (j < 32) { s = sbuf[w][j]; p = pbuf[w][j]; }
        else        { s = g_esrc[off0 + j]; p = edge_p(s, ad, aoff); }
        float2 xv = *(const float2*)(x + (size_t)s * 64 + 2 * lane);
        c00 += p.x * xv.x; c01 += p.x * xv.y;
        c10 += p.y * xv.x; c11 += p.y * xv.y;
        c20 += p.z * xv.x; c21 += p.z * xv.y;
        c30 += p.w * xv.x; c31 += p.w * xv.y;
    }
    yrow[0 * 32 + lane] = __floats2half2_rn(c00 * i0, c01 * i0);
    yrow[1 * 32 + lane] = __floats2half2_rn(c10 * i1, c11 * i1);
    yrow[2 * 32 + lane] = __floats2half2_rn(c20 * i2, c21 * i2);
    yrow[3 * 32 + lane] = __floats2half2_rn(c30 * i3, c31 * i3);
}

// ---------------- final GEMM over a row chunk: out = Y @ Wcat^T + bias ----------
#define YP2 68
#define CPF 68
#define XS_BYTES (128 * YP2 * 4)
#define WS_BYTES (64 * YP2 * 4)
#define CS_BYTES (128 * CPF * 4)
#define GEMMY_SMEM (XS_BYTES + WS_BYTES + CS_BYTES + 256)

__global__ __launch_bounds__(256, 2) void gemmy_k(float* __restrict__ out, int row0) {
    extern __shared__ char smem_c[];
    __half2* xs  = (__half2*)smem_c;
    __half2* ws  = (__half2*)(smem_c + XS_BYTES);
    float*   csm = (float*)(smem_c + XS_BYTES + WS_BYTES);
    float*   sb  = (float*)(smem_c + XS_BYTES + WS_BYTES + CS_BYTES);

    int tid = threadIdx.x;
    int lane = tid & 31, wid = tid >> 5;
    int gid = lane >> 2, tig = lane & 3;
    int warp_m = wid >> 1, warp_n = wid & 1;
    int rbase = row0 + blockIdx.x * 128;
    int rend  = row0 + CHUNK;              // store bound: this chunk's rows only
    if (tid < 64) sb[tid] = g_bias[tid];

    float acc[2][4][4];
    #pragma unroll
    for (int mf = 0; mf < 2; mf++)
        #pragma unroll
        for (int nf = 0; nf < 4; nf++)
            #pragma unroll
            for (int q = 0; q < 4; q++) acc[mf][nf][q] = 0.f;

    for (int ch = 0; ch < 8; ch++) {
        int kc0 = ch * 128;
        __syncthreads();
        #pragma unroll
        for (int i = 0; i < 8; i++) {
            int slot = tid + i * 256;
            int r = slot >> 4, q = slot & 15;
            uint4 v = make_uint4(0u, 0u, 0u, 0u);
            int row = rbase + r;
            if (row < N_NODES)   // overshoot rows may read garbage; stores guarded
                v = *(const uint4*)(g_y + (size_t)row * 1024 + kc0 + q * 8);
            *(uint4*)&xs[r * YP2 + q * 4] = v;
        }
        #pragma unroll
        for (int i = 0; i < 4; i++) {
            int slot = tid + i * 256;
            int o = slot >> 4, q = slot & 15;
            *(uint4*)&ws[o * YP2 + q * 4] =
                *(const uint4*)(g_wcat + o * 1024 + kc0 + q * 8);
        }
        __syncthreads();

        #pragma unroll
        for (int ks = 0; ks < 8; ks++) {
            int kc = ks * 8;
            unsigned a[2][4];
            #pragma unroll
            for (int mf = 0; mf < 2; mf++) {
                int arow = warp_m * 32 + mf * 16 + gid;
                a[mf][0] = *(unsigned*)&xs[arow * YP2 + kc + tig];
                a[mf][1] = *(unsigned*)&xs[(arow + 8) * YP2 + kc + tig];
                a[mf][2] = *(unsigned*)&xs[arow * YP2 + kc + tig + 4];
                a[mf][3] = *(unsigned*)&xs[(arow + 8) * YP2 + kc + tig + 4];
            }
            #pragma unroll
            for (int nf = 0; nf < 4; nf++) {
                int ncol = warp_n * 32 + nf * 8 + gid;
                unsigned b0 = *(unsigned*)&ws[ncol * YP2 + kc + tig];
                unsigned b1 = *(unsigned*)&ws[ncol * YP2 + kc + tig + 4];
                #pragma unroll
                for (int mf = 0; mf < 2; mf++)
                    mma_f16(acc[mf][nf], a[mf], b0, b1);
            }
        }
    }
    __syncthreads();

    #pragma unroll
    for (int mf = 0; mf < 2; mf++) {
        int r = warp_m * 32 + mf * 16 + gid;
        #pragma unroll
        for (int nf = 0; nf < 4; nf++) {
            int c = warp_n * 32 + nf * 8 + 2 * tig;
            *(float2*)&csm[r * CPF + c]       = make_float2(acc[mf][nf][0], acc[mf][nf][1]);
            *(float2*)&csm[(r + 8) * CPF + c] = make_float2(acc[mf][nf][2], acc[mf][nf][3]);
        }
    }
    __syncthreads();

    #pragma unroll
    for (int i = 0; i < 8; i++) {
        int slot = tid + i * 256;
        int row = slot >> 4, q = slot & 15;
        int grow = rbase + row;
        if (grow < rend && grow < N_NODES) {
            float4 v;
            v.x = csm[row * CPF + q * 4 + 0] + sb[q * 4 + 0];
            v.y = csm[row * CPF + q * 4 + 1] + sb[q * 4 + 1];
            v.z = csm[row * CPF + q * 4 + 2] + sb[q * 4 + 2];
            v.w = csm[row * CPF + q * 4 + 3] + sb[q * 4 + 3];
            *(float4*)(out + (size_t)grow * 64 + q * 4) = v;
        }
    }
}

// ---------------- launch ----------------
extern "C" void kernel_launch(void* const* d_in, const int* in_sizes, int n_in,
                              void* d_out, int out_size) {
    const float* x        = (const float*)d_in[0];
    const int*   modality = (const int*)d_in[1];
    const int*   isrc     = (const int*)d_in[2];
    const int*   idst     = (const int*)d_in[3];
    const int*   wsrc     = (const int*)d_in[4];
    const int*   wdst     = (const int*)d_in[5];
    const float* W_intra  = (const float*)d_in[6];
    const float* as_i     = (const float*)d_in[7];
    const float* ad_i     = (const float*)d_in[8];
    const float* b_i      = (const float*)d_in[9];
    const float* W_inter  = (const float*)d_in[10];
    const float* as_w     = (const float*)d_in[11];
    const float* ad_w     = (const float*)d_in[12];
    const float* b_w      = (const float*)d_in[13];
    float* out = (float*)d_out;

    cudaFuncSetAttribute(gemmy_k, cudaFuncAttributeMaxDynamicSharedMemorySize, GEMMY_SMEM);

    const int GY_GRID = (CHUNK + 127) / 128;   // 196

    if (g_ss.ok) {
        cudaEventRecord(g_ss.e1, 0);
        cudaStreamWaitEvent(g_ss.s2, g_ss.e1, 0);

        // s2: CSR build + Wcat (independent of x-chain)
        zero_k<<<(NSEG + 255) / 256, 256, 0, g_ss.s2>>>();
        wcat_k<<<(64 * 1024 + 255) / 256, 256, 0, g_ss.s2>>>(W_intra, W_inter);
        hist_k<<<(E_TOT + 255) / 256, 256, 0, g_ss.s2>>>(modality, idst, wdst);
        scan1_k<<<NB_SCAN, 256, 0, g_ss.s2>>>();
        scan2_k<<<1, 512, 0, g_ss.s2>>>();
        scan3_k<<<(NSEG + 255) / 256, 256, 0, g_ss.s2>>>();
        scat_k<<<(E_TOT + 255) / 256, 256, 0, g_ss.s2>>>(modality, isrc, idst, wsrc, wdst);
        cudaEventRecord(g_ss.e2, g_ss.s2);

        // main: logits chain, join CSR, then SAME-STREAM chunk interleave:
        // gemmy(c) reads the Y chunk aggx(c) just wrote while it is still
        // L2-resident (51 MB + 25 MB x < 126 MB L2). No events, no overlap —
        // the win is cache residency (R14's cross-stream variant regressed).
        fold_k<<<8, 256>>>(W_intra, as_i, ad_i, W_inter, as_w, ad_w, b_i, b_w);
        asd_k<<<(N_NODES + 255) / 256, 256>>>(x);
        cudaStreamWaitEvent(0, g_ss.e2, 0);
        for (int c = 0; c < NCHUNK; c++) {
            aggx_k<<<dim3(CHUNK / 4, 4), 128>>>(x, c * CHUNK);
            gemmy_k<<<GY_GRID, 256, GEMMY_SMEM>>>(out, c * CHUNK);
        }
    } else {
        // sequential fallback
        zero_k<<<(NSEG + 255) / 256, 256>>>();
        wcat_k<<<(64 * 1024 + 255) / 256, 256>>>(W_intra, W_inter);
        fold_k<<<8, 256>>>(W_intra, as_i, ad_i, W_inter, as_w, ad_w, b_i, b_w);
        asd_k<<<(N_NODES + 255) / 256, 256>>>(x);
        hist_k<<<(E_TOT + 255) / 256, 256>>>(modality, idst, wdst);
        scan1_k<<<NB_SCAN, 256>>>();
        scan2_k<<<1, 512>>>();
        scan3_k<<<(NSEG + 255) / 256, 256>>>();
        scat_k<<<(E_TOT + 255) / 256, 256>>>(modality, isrc, idst, wsrc, wdst);
        for (int c = 0; c < NCHUNK; c++) {
            aggx_k<<<dim3(CHUNK / 4, 4), 128>>>(x, c * CHUNK);
            gemmy_k<<<GY_GRID, 256, GEMMY_SMEM>>>(out, c * CHUNK);
        }
    }
}

// round 17
// speedup vs baseline: 1.3814x; 1.1190x over previous
#include <cuda_runtime.h>
#include <cuda_fp16.h>

#define N_NODES 100000
#define E_INTRA 1000000
#define E_INTER 500000
#define E_TOT   (E_INTRA + E_INTER)
#define NSEG    400000
#define NB_SCAN 391
#define SHIFT   10.0f

// ---------------- side stream (created once, pre-main) ----------------
struct SideStream {
    cudaStream_t s2 = nullptr;
    cudaEvent_t  e1 = nullptr, e2 = nullptr;
    bool ok = false;
    SideStream() {
        ok = (cudaStreamCreateWithFlags(&s2, cudaStreamNonBlocking) == cudaSuccess)
          && (cudaEventCreateWithFlags(&e1, cudaEventDisableTiming) == cudaSuccess)
          && (cudaEventCreateWithFlags(&e2, cudaEventDisableTiming) == cudaSuccess);
    }
};
static SideStream g_ss;

// ---------------- scratch ----------------
__device__ __half  g_y[(size_t)N_NODES * 1024];   // [n][p*256+h*64+c] fp16, 205MB
__device__ __half  g_wcat[64 * 1024];             // [o][p*256+h*64+c] fp16 (pre-transposed, /4)
__device__ float   g_as[N_NODES * 16];
__device__ float   g_ad[N_NODES * 16];
__device__ float   g_fold[64 * 32];
__device__ float   g_bias[64];
__device__ int     g_cnt[NSEG];
__device__ int     g_off[NSEG];
__device__ int     g_cur[NSEG];
__device__ int     g_bsum[NB_SCAN];
__device__ int     g_esrc[E_TOT];

// ---------------- fp16 mma helper ----------------
__device__ __forceinline__ void mma_f16(float* c, const unsigned* a,
                                        unsigned b0, unsigned b1) {
    asm("mma.sync.aligned.m16n8k16.row.col.f32.f16.f16.f32 "
        "{%0,%1,%2,%3},{%4,%5,%6,%7},{%8,%9},{%0,%1,%2,%3};"
        : "+f"(c[0]), "+f"(c[1]), "+f"(c[2]), "+f"(c[3])
        : "r"(a[0]), "r"(a[1]), "r"(a[2]), "r"(a[3]), "r"(b0), "r"(b1));
}

// ---------------- small setup kernels ----------------
__global__ void zero_k() {
    int i = blockIdx.x * blockDim.x + threadIdx.x;
    if (i < NSEG) g_cnt[i] = 0;
}

// Wcat[o][k], k=(p,h,c): W_p[c, h*64+o] * 0.25 (head-avg folded in)
__global__ void wcat_k(const float* __restrict__ Wi, const float* __restrict__ Ww) {
    int idx = blockIdx.x * blockDim.x + threadIdx.x;
    if (idx >= 64 * 1024) return;
    int o = idx >> 10, k = idx & 1023;
    int p = k >> 8, h = (k >> 6) & 3, c = k & 63;
    float v = (p < 3) ? Wi[p * 16384 + c * 256 + h * 64 + o]
                      : Ww[c * 256 + h * 64 + o];
    g_wcat[idx] = __float2half_rn(0.25f * v);
}

__global__ void fold_k(const float* __restrict__ Wi, const float* __restrict__ asi,
                       const float* __restrict__ adi, const float* __restrict__ Ww,
                       const float* __restrict__ asw, const float* __restrict__ adw,
                       const float* __restrict__ bi, const float* __restrict__ bw) {
    int idx = blockIdx.x * blockDim.x + threadIdx.x;
    if (idx < 64) g_bias[idx] = bi[idx] + bi[64 + idx] + bi[128 + idx] + bw[idx];
    if (idx >= 64 * 32) return;
    int f = idx >> 5, o = idx & 31;
    int sd = o >> 4, p = (o >> 2) & 3, h = o & 3;
    const float* W = (p < 3) ? (Wi + p * 64 * 256) : Ww;
    const float* att;
    if (p < 3) att = (sd ? adi : asi) + p * 4 * 64 + h * 64;
    else       att = (sd ? adw : asw) + h * 64;
    const float* wr = W + f * 256 + h * 64;
    float s = 0.f;
    #pragma unroll 16
    for (int c = 0; c < 64; c++) s += wr[c] * att[c];
    g_fold[f * 32 + o] = s;
}

__global__ __launch_bounds__(256) void asd_k(const float* __restrict__ x) {
    __shared__ float sf[64 * 32];
    for (int i = threadIdx.x; i < 2048; i += 256) sf[i] = g_fold[i];
    __syncthreads();
    int n = blockIdx.x * blockDim.x + threadIdx.x;
    if (n >= N_NODES) return;
    float acc[32];
    #pragma unroll
    for (int o = 0; o < 32; o++) acc[o] = 0.f;
    const float4* xr = (const float4*)(x + (size_t)n * 64);
    #pragma unroll
    for (int f4 = 0; f4 < 16; f4++) {
        float4 xv = __ldg(xr + f4);
        int f = f4 * 4;
        #pragma unroll
        for (int o = 0; o < 32; o++) {
            acc[o] += xv.x * sf[(f + 0) * 32 + o] + xv.y * sf[(f + 1) * 32 + o]
                    + xv.z * sf[(f + 2) * 32 + o] + xv.w * sf[(f + 3) * 32 + o];
        }
    }
    float4* as4 = (float4*)(g_as + n * 16);
    float4* ad4 = (float4*)(g_ad + n * 16);
    #pragma unroll
    for (int q = 0; q < 4; q++) {
        as4[q] = make_float4(acc[q * 4 + 0], acc[q * 4 + 1], acc[q * 4 + 2], acc[q * 4 + 3]);
        ad4[q] = make_float4(acc[16 + q * 4 + 0], acc[16 + q * 4 + 1], acc[16 + q * 4 + 2], acc[16 + q * 4 + 3]);
    }
}

// ---------------- CSR build ----------------
__global__ void hist_k(const int* __restrict__ mod, const int* __restrict__ idst,
                       const int* __restrict__ wdst) {
    int e = blockIdx.x * blockDim.x + threadIdx.x;
    if (e >= E_TOT) return;
    int key;
    if (e < E_INTRA) key = __ldg(mod + e) * N_NODES + __ldg(idst + e);
    else             key = 3 * N_NODES + __ldg(wdst + e - E_INTRA);
    atomicAdd(&g_cnt[key], 1);
}

__global__ __launch_bounds__(256) void scan1_k() {
    __shared__ int sw[8];
    int b = blockIdx.x, t = threadIdx.x;
    int lane = t & 31, wid = t >> 5;
    int base = b * 1024 + t * 4;
    int v0 = (base + 0 < NSEG) ? g_cnt[base + 0] : 0;
    int v1 = (base + 1 < NSEG) ? g_cnt[base + 1] : 0;
    int v2 = (base + 2 < NSEG) ? g_cnt[base + 2] : 0;
    int v3 = (base + 3 < NSEG) ? g_cnt[base + 3] : 0;
    int tsum = v0 + v1 + v2 + v3;
    int incl = tsum;
    #pragma unroll
    for (int o = 1; o < 32; o <<= 1) {
        int n = __shfl_up_sync(0xffffffffu, incl, o);
        if (lane >= o) incl += n;
    }
    if (lane == 31) sw[wid] = incl;
    __syncthreads();
    int wbase = 0;
    for (int i = 0; i < 8; i++) if (i < wid) wbase += sw[i];
    int texcl = wbase + incl - tsum;
    if (base + 0 < NSEG) g_off[base + 0] = texcl;
    if (base + 1 < NSEG) g_off[base + 1] = texcl + v0;
    if (base + 2 < NSEG) g_off[base + 2] = texcl + v0 + v1;
    if (base + 3 < NSEG) g_off[base + 3] = texcl + v0 + v1 + v2;
    if (t == 255) g_bsum[b] = texcl + tsum;
}

__global__ __launch_bounds__(512) void scan2_k() {
    __shared__ int sw[16];
    int t = threadIdx.x, lane = t & 31, wid = t >> 5;
    int v = (t < NB_SCAN) ? g_bsum[t] : 0;
    int incl = v;
    #pragma unroll
    for (int o = 1; o < 32; o <<= 1) {
        int n = __shfl_up_sync(0xffffffffu, incl, o);
        if (lane >= o) incl += n;
    }
    if (lane == 31) sw[wid] = incl;
    __syncthreads();
    int wbase = 0;
    for (int i = 0; i < 16; i++) if (i < wid) wbase += sw[i];
    if (t < NB_SCAN) g_bsum[t] = wbase + incl - v;
}

__global__ void scan3_k() {
    int i = blockIdx.x * blockDim.x + threadIdx.x;
    if (i >= NSEG) return;
    int o = g_off[i] + g_bsum[i >> 10];
    g_off[i] = o;
    g_cur[i] = o;
}

__global__ void scat_k(const int* __restrict__ mod,
                       const int* __restrict__ isrc, const int* __restrict__ idst,
                       const int* __restrict__ wsrc, const int* __restrict__ wdst) {
    int e = blockIdx.x * blockDim.x + threadIdx.x;
    if (e >= E_TOT) return;
    int key, s;
    if (e < E_INTRA) {
        key = __ldg(mod + e) * N_NODES + __ldg(idst + e);
        s = __ldg(isrc + e);
    } else {
        key = 3 * N_NODES + __ldg(wdst + e - E_INTRA);
        s = __ldg(wsrc + e - E_INTRA);
    }
    int pos = atomicAdd(&g_cur[key], 1);
    g_esrc[pos] = s;
}

// ---------------- x-space softmax aggregation: Y[d, pass, h, :] ----------------
__device__ __forceinline__ float4 edge_p(int s, float4 ad, int aoff) {
    float4 as = *(const float4*)(g_as + s * 16 + aoff);
    float v0 = as.x + ad.x; v0 = v0 > 0.f ? v0 : 0.2f * v0;
    float v1 = as.y + ad.y; v1 = v1 > 0.f ? v1 : 0.2f * v1;
    float v2 = as.z + ad.z; v2 = v2 > 0.f ? v2 : 0.2f * v2;
    float v3 = as.w + ad.w; v3 = v3 > 0.f ? v3 : 0.2f * v3;
    return make_float4(__expf(v0 - SHIFT), __expf(v1 - SHIFT),
                       __expf(v2 - SHIFT), __expf(v3 - SHIFT));
}

__global__ __launch_bounds__(128) void aggx_k(const float* __restrict__ x) {
    __shared__ float4 pbuf[4][32];
    __shared__ int    sbuf[4][32];
    int pass = blockIdx.y;
    int w = threadIdx.x >> 5;
    int d = blockIdx.x * 4 + w;      // grid exact: d < N_NODES
    int lane = threadIdx.x & 31;
    int seg = pass * N_NODES + d;
    int off0 = g_off[seg];
    int off1 = (seg + 1 < NSEG) ? g_off[seg + 1] : E_TOT;
    int deg = off1 - off0;
    int aoff = pass * 4;
    __half2* yrow = (__half2*)(g_y + (size_t)d * 1024 + pass * 256);

    if (deg == 0) {
        __half2 z = __floats2half2_rn(0.f, 0.f);
        #pragma unroll
        for (int h = 0; h < 4; h++) yrow[h * 32 + lane] = z;
        return;
    }

    float4 ad = *(const float4*)(g_ad + d * 16 + aoff);

    // phase A: lane-parallel edge logits; stash (p, s) for first 32 edges
    float d0 = 0.f, d1 = 0.f, d2 = 0.f, d3 = 0.f;
    for (int j = lane; j < deg; j += 32) {
        int s = g_esrc[off0 + j];
        float4 p = edge_p(s, ad, aoff);
        if (j < 32) { pbuf[w][j] = p; sbuf[w][j] = s; }
        d0 += p.x; d1 += p.y; d2 += p.z; d3 += p.w;
    }
    #pragma unroll
    for (int o = 16; o > 0; o >>= 1) {
        d0 += __shfl_xor_sync(0xffffffffu, d0, o);
        d1 += __shfl_xor_sync(0xffffffffu, d1, o);
        d2 += __shfl_xor_sync(0xffffffffu, d2, o);
        d3 += __shfl_xor_sync(0xffffffffu, d3, o);
    }
    __syncwarp();
    float i0 = 1.f / fmaxf(d0, 1e-16f);   // 0.25 folded into Wcat
    float i1 = 1.f / fmaxf(d1, 1e-16f);
    float i2 = 1.f / fmaxf(d2, 1e-16f);
    float i3 = 1.f / fmaxf(d3, 1e-16f);

    // phase B: lane covers x cols 2*lane, 2*lane+1 (x L2-resident, 25.6MB)
    float c00 = 0.f, c01 = 0.f, c10 = 0.f, c11 = 0.f;
    float c20 = 0.f, c21 = 0.f, c30 = 0.f, c31 = 0.f;
    for (int j = 0; j < deg; j++) {
        int s; float4 p;
        if (j < 32) { s = sbuf[w][j]; p = pbuf[w][j]; }
        else        { s = g_esrc[off0 + j]; p = edge_p(s, ad, aoff); }
        float2 xv = *(const float2*)(x + (size_t)s * 64 + 2 * lane);
        c00 += p.x * xv.x; c01 += p.x * xv.y;
        c10 += p.y * xv.x; c11 += p.y * xv.y;
        c20 += p.z * xv.x; c21 += p.z * xv.y;
        c30 += p.w * xv.x; c31 += p.w * xv.y;
    }
    yrow[0 * 32 + lane] = __floats2half2_rn(c00 * i0, c01 * i0);
    yrow[1 * 32 + lane] = __floats2half2_rn(c10 * i1, c11 * i1);
    yrow[2 * 32 + lane] = __floats2half2_rn(c20 * i2, c21 * i2);
    yrow[3 * 32 + lane] = __floats2half2_rn(c30 * i3, c31 * i3);
}

// ---------------- final GEMM: out[N,64] = Y[N,1024] @ Wcat^T + bias ----------------
#define YP2 68
#define CPF 68
#define XS_BYTES (128 * YP2 * 4)
#define WS_BYTES (64 * YP2 * 4)
#define CS_BYTES (128 * CPF * 4)
#define GEMMY_SMEM (XS_BYTES + WS_BYTES + CS_BYTES + 256)

__global__ __launch_bounds__(256, 2) void gemmy_k(float* __restrict__ out) {
    extern __shared__ char smem_c[];
    __half2* xs  = (__half2*)smem_c;
    __half2* ws  = (__half2*)(smem_c + XS_BYTES);
    float*   csm = (float*)(smem_c + XS_BYTES + WS_BYTES);
    float*   sb  = (float*)(smem_c + XS_BYTES + WS_BYTES + CS_BYTES);

    int tid = threadIdx.x;
    int lane = tid & 31, wid = tid >> 5;
    int gid = lane >> 2, tig = lane & 3;
    int warp_m = wid >> 1, warp_n = wid & 1;   // 4 x 2 warp grid
    int row0 = blockIdx.x * 128;
    if (tid < 64) sb[tid] = g_bias[tid];

    float acc[2][4][4];
    #pragma unroll
    for (int mf = 0; mf < 2; mf++)
        #pragma unroll
        for (int nf = 0; nf < 4; nf++)
            #pragma unroll
            for (int q = 0; q < 4; q++) acc[mf][nf][q] = 0.f;

    for (int ch = 0; ch < 8; ch++) {           // K = 1024 in 8 chunks of 128
        int kc0 = ch * 128;
        __syncthreads();
        #pragma unroll
        for (int i = 0; i < 8; i++) {
            int slot = tid + i * 256;
            int r = slot >> 4, q = slot & 15;
            uint4 v = make_uint4(0u, 0u, 0u, 0u);
            int row = row0 + r;
            if (row < N_NODES)
                v = *(const uint4*)(g_y + (size_t)row * 1024 + kc0 + q * 8);
            *(uint4*)&xs[r * YP2 + q * 4] = v;
        }
        #pragma unroll
        for (int i = 0; i < 4; i++) {
            int slot = tid + i * 256;
            int o = slot >> 4, q = slot & 15;
            *(uint4*)&ws[o * YP2 + q * 4] =
                *(const uint4*)(g_wcat + o * 1024 + kc0 + q * 8);
        }
        __syncthreads();

        #pragma unroll
        for (int ks = 0; ks < 8; ks++) {       // 128 k = 8 x k16
            int kc = ks * 8;
            unsigned a[2][4];
            #pragma unroll
            for (int mf = 0; mf < 2; mf++) {
                int arow = warp_m * 32 + mf * 16 + gid;
                a[mf][0] = *(unsigned*)&xs[arow * YP2 + kc + tig];
                a[mf][1] = *(unsigned*)&xs[(arow + 8) * YP2 + kc + tig];
                a[mf][2] = *(unsigned*)&xs[arow * YP2 + kc + tig + 4];
                a[mf][3] = *(unsigned*)&xs[(arow + 8) * YP2 + kc + tig + 4];
            }
            #pragma unroll
            for (int nf = 0; nf < 4; nf++) {
                int ncol = warp_n * 32 + nf * 8 + gid;
                unsigned b0 = *(unsigned*)&ws[ncol * YP2 + kc + tig];
                unsigned b1 = *(unsigned*)&ws[ncol * YP2 + kc + tig + 4];
                #pragma unroll
                for (int mf = 0; mf < 2; mf++)
                    mma_f16(acc[mf][nf], a[mf], b0, b1);
            }
        }
    }
    __syncthreads();

    // stage C (fp32) then coalesced biased store
    #pragma unroll
    for (int mf = 0; mf < 2; mf++) {
        int r = warp_m * 32 + mf * 16 + gid;
        #pragma unroll
        for (int nf = 0; nf < 4; nf++) {
            int c = warp_n * 32 + nf * 8 + 2 * tig;
            *(float2*)&csm[r * CPF + c]       = make_float2(acc[mf][nf][0], acc[mf][nf][1]);
            *(float2*)&csm[(r + 8) * CPF + c] = make_float2(acc[mf][nf][2], acc[mf][nf][3]);
        }
    }
    __syncthreads();

    #pragma unroll
    for (int i = 0; i < 8; i++) {
        int slot = tid + i * 256;
        int row = slot >> 4, q = slot & 15;
        if (row0 + row < N_NODES) {
            float4 v;
            v.x = csm[row * CPF + q * 4 + 0] + sb[q * 4 + 0];
            v.y = csm[row * CPF + q * 4 + 1] + sb[q * 4 + 1];
            v.z = csm[row * CPF + q * 4 + 2] + sb[q * 4 + 2];
            v.w = csm[row * CPF + q * 4 + 3] + sb[q * 4 + 3];
            *(float4*)(out + (size_t)(row0 + row) * 64 + q * 4) = v;
        }
    }
}

// ---------------- launch ----------------
extern "C" void kernel_launch(void* const* d_in, const int* in_sizes, int n_in,
                              void* d_out, int out_size) {
    const float* x        = (const float*)d_in[0];
    const int*   modality = (const int*)d_in[1];
    const int*   isrc     = (const int*)d_in[2];
    const int*   idst     = (const int*)d_in[3];
    const int*   wsrc     = (const int*)d_in[4];
    const int*   wdst     = (const int*)d_in[5];
    const float* W_intra  = (const float*)d_in[6];
    const float* as_i     = (const float*)d_in[7];
    const float* ad_i     = (const float*)d_in[8];
    const float* b_i      = (const float*)d_in[9];
    const float* W_inter  = (const float*)d_in[10];
    const float* as_w     = (const float*)d_in[11];
    const float* ad_w     = (const float*)d_in[12];
    const float* b_w      = (const float*)d_in[13];
    float* out = (float*)d_out;

    cudaFuncSetAttribute(gemmy_k, cudaFuncAttributeMaxDynamicSharedMemorySize, GEMMY_SMEM);

    if (g_ss.ok) {
        cudaEventRecord(g_ss.e1, 0);
        cudaStreamWaitEvent(g_ss.s2, g_ss.e1, 0);

        // s2: CSR chain FIRST (it is the pre-aggx critical path); wcat last
        // (only needed by gemmy, much later).
        zero_k<<<(NSEG + 255) / 256, 256, 0, g_ss.s2>>>();
        hist_k<<<(E_TOT + 255) / 256, 256, 0, g_ss.s2>>>(modality, idst, wdst);
        scan1_k<<<NB_SCAN, 256, 0, g_ss.s2>>>();
        scan2_k<<<1, 512, 0, g_ss.s2>>>();
        scan3_k<<<(NSEG + 255) / 256, 256, 0, g_ss.s2>>>();
        scat_k<<<(E_TOT + 255) / 256, 256, 0, g_ss.s2>>>(modality, isrc, idst, wsrc, wdst);
        cudaEventRecord(g_ss.e2, g_ss.s2);
        wcat_k<<<(64 * 1024 + 255) / 256, 256, 0, g_ss.s2>>>(W_intra, W_inter);

        // main: logits chain, join CSR, then aggregate + GEMM (R13 winner)
        fold_k<<<8, 256>>>(W_intra, as_i, ad_i, W_inter, as_w, ad_w, b_i, b_w);
        asd_k<<<(N_NODES + 255) / 256, 256>>>(x);
        cudaStreamWaitEvent(0, g_ss.e2, 0);
        aggx_k<<<dim3(N_NODES / 4, 4), 128>>>(x);
        // gemmy also needs wcat: it completed on s2 well before aggx finishes,
        // but order it formally via the stream-0 wait below.
        cudaEventRecord(g_ss.e1, g_ss.s2);
        cudaStreamWaitEvent(0, g_ss.e1, 0);
        gemmy_k<<<(N_NODES + 127) / 128, 256, GEMMY_SMEM>>>(out);
    } else {
        zero_k<<<(NSEG + 255) / 256, 256>>>();
        wcat_k<<<(64 * 1024 + 255) / 256, 256>>>(W_intra, W_inter);
        fold_k<<<8, 256>>>(W_intra, as_i, ad_i, W_inter, as_w, ad_w, b_i, b_w);
        asd_k<<<(N_NODES + 255) / 256, 256>>>(x);
        hist_k<<<(E_TOT + 255) / 256, 256>>>(modality, idst, wdst);
        scan1_k<<<NB_SCAN, 256>>>();
        scan2_k<<<1, 512>>>();
        scan3_k<<<(NSEG + 255) / 256, 256>>>();
        scat_k<<<(E_TOT + 255) / 256, 256>>>(modality, isrc, idst, wsrc, wdst);
        aggx_k<<<dim3(N_NODES / 4, 4), 128>>>(x);
        gemmy_k<<<(N_NODES + 127) / 128, 256, GEMMY_SMEM>>>(out);
    }
}